// round 6
// baseline (speedup 1.0000x reference)
#include <cuda_runtime.h>
#include <cuda_bf16.h>
#include <mma.h>
#include <math.h>
#include <cstdint>
#include <cstddef>

using namespace nvcuda;

// ---------------------------------------------------------------------------
// Problem constants: B=8, N=2048, H=2048, E=4, I=2048
// Per expert: rows R = B*N/E = 4096, K1 = H = 2048 (GEMM1, fused gate/up),
//             K2 = I = 2048, N2 = H = 2048 (GEMM2).
// ---------------------------------------------------------------------------
#define EXPERTS 4
#define RDIM    4096          // rows per expert
#define HDIM    2048
#define IDIM    2048

// ---------------------- scratch (__device__ globals) -----------------------
__device__ __nv_bfloat16 g_xh [ (size_t)EXPERTS * RDIM * HDIM ];      // 67 MB
__device__ __nv_bfloat16 g_xl [ (size_t)EXPERTS * RDIM * HDIM ];
__device__ __nv_bfloat16 g_wgh[ (size_t)EXPERTS * HDIM * 2 * IDIM ];  // 67 MB
__device__ __nv_bfloat16 g_wgl[ (size_t)EXPERTS * HDIM * 2 * IDIM ];
__device__ __nv_bfloat16 g_wdh[ (size_t)EXPERTS * IDIM * HDIM ];      // 34 MB
__device__ __nv_bfloat16 g_wdl[ (size_t)EXPERTS * IDIM * HDIM ];
__device__ __nv_bfloat16 g_ih [ (size_t)EXPERTS * RDIM * IDIM ];      // 67 MB
__device__ __nv_bfloat16 g_il [ (size_t)EXPERTS * RDIM * IDIM ];

// ---------------------------- helpers --------------------------------------
__device__ __forceinline__ void split2(float v, __nv_bfloat16& hi, __nv_bfloat16& lo) {
    hi = __float2bfloat16(v);
    lo = __float2bfloat16(v - __bfloat162float(hi));
}

// Split a float4 into packed bf16x2 hi/lo pairs.
__device__ __forceinline__ void split4(float4 v, uint32_t& hi01, uint32_t& hi23,
                                       uint32_t& lo01, uint32_t& lo23) {
    __nv_bfloat16 h0, h1, h2, h3, l0, l1, l2, l3;
    split2(v.x, h0, l0);
    split2(v.y, h1, l1);
    split2(v.z, h2, l2);
    split2(v.w, h3, l3);
    __nv_bfloat162 H01 = __halves2bfloat162(h0, h1);
    __nv_bfloat162 H23 = __halves2bfloat162(h2, h3);
    __nv_bfloat162 L01 = __halves2bfloat162(l0, l1);
    __nv_bfloat162 L23 = __halves2bfloat162(l2, l3);
    hi01 = *(uint32_t*)&H01;  hi23 = *(uint32_t*)&H23;
    lo01 = *(uint32_t*)&L01;  lo23 = *(uint32_t*)&L23;
}

__device__ __forceinline__ float silu_mul(float g, float u) {
    return (g * __frcp_rn(1.0f + __expf(-g))) * u;
}

__device__ __forceinline__ void cp_async16(void* smem, const void* gmem) {
    uint32_t s = (uint32_t)__cvta_generic_to_shared(smem);
    asm volatile("cp.async.cg.shared.global [%0], [%1], 16;\n" :: "r"(s), "l"(gmem));
}
__device__ __forceinline__ void cp_commit() { asm volatile("cp.async.commit_group;\n"); }
template<int NG> __device__ __forceinline__ void cp_wait() {
    asm volatile("cp.async.wait_group %0;\n" :: "n"(NG));
}

// ------------------------- elementwise kernels ------------------------------
// Gather tokens per expert and split fp32 -> bf16 hi/lo (vectorized).
// x is [B=8][N=2048][H=2048]; expert e = n & 3, g = n >> 2, r = b*512 + g.
__global__ void split_x_kernel(const float4* __restrict__ x,
                               uint32_t* __restrict__ xh,   // bf16x2 view
                               uint32_t* __restrict__ xl) {
    size_t v = (size_t)blockIdx.x * 256 + threadIdx.x;     // vec4 index, < 8*2048*512
    int h4 = (int)(v & 511);                               // h/4
    int n  = (int)((v >> 9) & 2047);
    int b  = (int)(v >> 20);
    int e  = n & 3;
    int g  = n >> 2;
    size_t r = (size_t)b * 512 + g;
    size_t dst2 = (((size_t)e * RDIM + r) << 10) + h4 * 2; // bf16x2 units (1024/row)
    float4 val = x[v];
    uint32_t h01, h23, l01, l23;
    split4(val, h01, h23, l01, l23);
    xh[dst2] = h01;  xh[dst2 + 1] = h23;
    xl[dst2] = l01;  xl[dst2 + 1] = l23;
}

// Straight layout-preserving split (weights). n4 = element count / 4.
__global__ void split_kernel(const float4* __restrict__ src,
                             uint32_t* __restrict__ h,
                             uint32_t* __restrict__ l,
                             size_t n4) {
    size_t v = (size_t)blockIdx.x * 256 + threadIdx.x;
    if (v >= n4) return;
    uint32_t h01, h23, l01, l23;
    split4(src[v], h01, h23, l01, l23);
    h[v * 2] = h01;  h[v * 2 + 1] = h23;
    l[v * 2] = l01;  l[v * 2 + 1] = l23;
}

// ---------------------------------------------------------------------------
// GEMM1 (fused): per expert, A [4096 x 2048] (hi/lo) x Wgu [2048 x 4096].
// Block tile = 128 rows x 64 inter-cols; CTA accumulates gate tile (cols
// c..c+63) AND up tile (cols c+2048..), applies silu(gate)*up on the
// accumulator fragments, splits to bf16 hi/lo, stores to ih/il.
// Pipeline: 4 stages, prefetch distance 3, ONE __syncthreads per k-iter
// (wait -> sync -> issue(t+3) -> compute; write of stage (t+3)%4 == (t-1)%4
//  happens after sync(t), i.e. after all warps finished reading it at t-1).
// ---------------------------------------------------------------------------
#define F_SA    (128 * 40)    // A tile per stream: 128 x (32+8)
#define F_SB    (32 * 72)     // B tile per stream per half: 32 x (64+8)
#define F_STAGE (2 * F_SA + 4 * F_SB)        // 19456 elems
#define F_NST   4
#define SMEM1_BYTES (F_NST * F_STAGE * 2)    // 155648 B
#define GROUP_M 8

__device__ __forceinline__ void f_load_tiles(
    __nv_bfloat16* stage,
    const __nv_bfloat16* Ah, const __nv_bfloat16* Al,
    const __nv_bfloat16* Bh, const __nv_bfloat16* Bl,   // full 2048x4096 panel
    int rowBase, int colI, int k0, int tid)
{
    __nv_bfloat16* sAh = stage;
    __nv_bfloat16* sAl = stage + F_SA;
    __nv_bfloat16* sBgh = stage + 2 * F_SA;
    __nv_bfloat16* sBgl = sBgh + F_SB;
    __nv_bfloat16* sBuh = sBgl + F_SB;
    __nv_bfloat16* sBul = sBuh + F_SB;
    #pragma unroll
    for (int i = tid; i < 512; i += 256) {        // A: 128x32
        int r  = i >> 2;
        int cc = (i & 3) * 8;
        size_t g = (size_t)(rowBase + r) * HDIM + k0 + cc;
        int s = r * 40 + cc;
        cp_async16(sAh + s, Ah + g);
        cp_async16(sAl + s, Al + g);
    }
    #pragma unroll
    for (int i = tid; i < 256; i += 256) {        // B halves: 32x64 each
        int r  = i >> 3;
        int cc = (i & 7) * 8;
        int s = r * 72 + cc;
        size_t gg = (size_t)(k0 + r) * (2 * IDIM) + colI + cc;
        cp_async16(sBgh + s, Bh + gg);
        cp_async16(sBgl + s, Bl + gg);
        size_t gu = gg + IDIM;                     // up half at col +2048
        cp_async16(sBuh + s, Bh + gu);
        cp_async16(sBul + s, Bl + gu);
    }
}

__global__ __launch_bounds__(256, 1)
void gemm1_fused(const __nv_bfloat16* __restrict__ Ah, const __nv_bfloat16* __restrict__ Al,
                 const __nv_bfloat16* __restrict__ Bh, const __nv_bfloat16* __restrict__ Bl,
                 __nv_bfloat16* __restrict__ Ih, __nv_bfloat16* __restrict__ Il)
{
    extern __shared__ __nv_bfloat16 smem[];

    const int e = blockIdx.z;
    const __nv_bfloat16* eAh = Ah + (size_t)e * RDIM * HDIM;
    const __nv_bfloat16* eAl = Al + (size_t)e * RDIM * HDIM;
    const __nv_bfloat16* eBh = Bh + (size_t)e * HDIM * 2 * IDIM;
    const __nv_bfloat16* eBl = Bl + (size_t)e * HDIM * 2 * IDIM;

    // GROUP_M swizzle over 32 row-tiles x 32 col-tiles (64-wide inter cols).
    const int num_pid_m = RDIM / 128;   // 32
    const int num_pid_n = IDIM / 64;    // 32
    const int pid = blockIdx.x;
    const int num_pid_in_group = GROUP_M * num_pid_n;
    const int group_id = pid / num_pid_in_group;
    const int first_pid_m = group_id * GROUP_M;
    const int group_size_m = min(num_pid_m - first_pid_m, GROUP_M);
    const int pid_m = first_pid_m + (pid % group_size_m);
    const int pid_n = (pid % num_pid_in_group) / group_size_m;

    const int tid  = threadIdx.x;
    const int warp = tid >> 5;
    const int lane = tid & 31;
    const int wm   = warp & 3;    // 0..3 (32 rows each)
    const int wn   = warp >> 2;   // 0..1 (32 cols each)
    const int rowBase = pid_m * 128;
    const int colI    = pid_n * 64;    // inter-column base (gate); up at +2048

    wmma::fragment<wmma::accumulator, 16, 16, 16, float> acc_g[2][2], acc_u[2][2];
    #pragma unroll
    for (int i = 0; i < 2; ++i)
        #pragma unroll
        for (int j = 0; j < 2; ++j) {
            wmma::fill_fragment(acc_g[i][j], 0.0f);
            wmma::fill_fragment(acc_u[i][j], 0.0f);
        }

    const int T = HDIM / 32;   // 64

    // Prologue: prefetch stages 0,1,2 (distance 3).
    f_load_tiles(smem + 0 * F_STAGE, eAh, eAl, eBh, eBl, rowBase, colI, 0, tid);
    cp_commit();
    f_load_tiles(smem + 1 * F_STAGE, eAh, eAl, eBh, eBl, rowBase, colI, 32, tid);
    cp_commit();
    f_load_tiles(smem + 2 * F_STAGE, eAh, eAl, eBh, eBl, rowBase, colI, 64, tid);
    cp_commit();

    for (int t = 0; t < T; ++t) {
        // Wait until stage t's group is complete (pending <= remaining groups).
        if (t + 2 < T)      cp_wait<2>();
        else if (t + 1 < T) cp_wait<1>();
        else                cp_wait<0>();
        __syncthreads();    // publish stage t; all warps done reading (t-1)%4

        if (t + 3 < T) {    // safe: after sync(t), stage (t+3)%4==(t-1)%4 is free
            f_load_tiles(smem + ((t + 3) % F_NST) * F_STAGE,
                         eAh, eAl, eBh, eBl, rowBase, colI, (t + 3) * 32, tid);
            cp_commit();
        }

        __nv_bfloat16* stage = smem + (t % F_NST) * F_STAGE;
        const __nv_bfloat16* pAh  = stage;
        const __nv_bfloat16* pAl  = stage + F_SA;
        const __nv_bfloat16* pBgh = stage + 2 * F_SA;
        const __nv_bfloat16* pBgl = pBgh + F_SB;
        const __nv_bfloat16* pBuh = pBgl + F_SB;
        const __nv_bfloat16* pBul = pBuh + F_SB;

        #pragma unroll
        for (int kk = 0; kk < 2; ++kk) {
            wmma::fragment<wmma::matrix_a, 16, 16, 16, __nv_bfloat16, wmma::row_major> ah[2], al[2];
            #pragma unroll
            for (int i = 0; i < 2; ++i) {
                const int ro = (wm * 32 + i * 16) * 40 + kk * 16;
                wmma::load_matrix_sync(ah[i], pAh + ro, 40);
                wmma::load_matrix_sync(al[i], pAl + ro, 40);
            }
            #pragma unroll
            for (int j = 0; j < 2; ++j) {
                const int bo = kk * 16 * 72 + wn * 32 + j * 16;
                wmma::fragment<wmma::matrix_b, 16, 16, 16, __nv_bfloat16, wmma::row_major> bh, bl;
                // gate half
                wmma::load_matrix_sync(bh, pBgh + bo, 72);
                wmma::load_matrix_sync(bl, pBgl + bo, 72);
                #pragma unroll
                for (int i = 0; i < 2; ++i) {
                    wmma::mma_sync(acc_g[i][j], ah[i], bh, acc_g[i][j]);
                    wmma::mma_sync(acc_g[i][j], al[i], bh, acc_g[i][j]);
                    wmma::mma_sync(acc_g[i][j], ah[i], bl, acc_g[i][j]);
                }
                // up half
                wmma::load_matrix_sync(bh, pBuh + bo, 72);
                wmma::load_matrix_sync(bl, pBul + bo, 72);
                #pragma unroll
                for (int i = 0; i < 2; ++i) {
                    wmma::mma_sync(acc_u[i][j], ah[i], bh, acc_u[i][j]);
                    wmma::mma_sync(acc_u[i][j], al[i], bh, acc_u[i][j]);
                    wmma::mma_sync(acc_u[i][j], ah[i], bl, acc_u[i][j]);
                }
            }
        }
        // no trailing sync: next iteration's sync provides the ordering
    }

    // --- fused epilogue: inter = silu(gate) * up, split hi/lo, store ---
    #pragma unroll
    for (int i = 0; i < 2; ++i)
        #pragma unroll
        for (int j = 0; j < 2; ++j)
            #pragma unroll
            for (int k = 0; k < acc_g[i][j].num_elements; ++k)
                acc_g[i][j].x[k] = silu_mul(acc_g[i][j].x[k], acc_u[i][j].x[k]);

    __syncthreads();   // all warps done with last mainloop stage before smem reuse

    // Stage per-warp 32x32 fp32 tile in smem (stride 36), then split+store.
    float* ws = (float*)smem + warp * 32 * 36;
    #pragma unroll
    for (int i = 0; i < 2; ++i)
        #pragma unroll
        for (int j = 0; j < 2; ++j)
            wmma::store_matrix_sync(ws + (i * 16) * 36 + j * 16, acc_g[i][j], 36,
                                    wmma::mem_row_major);
    __syncwarp();

    {
        const int r  = rowBase + wm * 32 + lane;          // this thread's row
        const int c0 = colI + wn * 32;                    // 32 cols
        const float* src = ws + lane * 36;
        size_t dst2 = (((size_t)e * RDIM + r) << 10) + (c0 >> 1);  // bf16x2 units
        uint32_t* ih2 = (uint32_t*)Ih;
        uint32_t* il2 = (uint32_t*)Il;
        #pragma unroll
        for (int c = 0; c < 32; c += 4) {
            float4 v = make_float4(src[c], src[c + 1], src[c + 2], src[c + 3]);
            uint32_t h01, h23, l01, l23;
            split4(v, h01, h23, l01, l23);
            ih2[dst2 + (c >> 1)]     = h01;
            ih2[dst2 + (c >> 1) + 1] = h23;
            il2[dst2 + (c >> 1)]     = l01;
            il2[dst2 + (c >> 1) + 1] = l23;
        }
    }
}

// ---------------------------------------------------------------------------
// GEMM2: C = inter (hi/lo) @ Wd (hi/lo), scatter rows to token order.
// Block tile 128x128x32, 8 warps (4x2), warp 32x64. Same 4-stage/1-sync
// pipeline as GEMM1.
// ---------------------------------------------------------------------------
#define SA_ELEMS (128 * 40)
#define SB_ELEMS (32 * 136)
#define STAGE_ELEMS (2 * SA_ELEMS + 2 * SB_ELEMS)
#define NSTAGES 4
#define SMEM_BYTES (NSTAGES * STAGE_ELEMS * 2)   // 151552 B

__device__ __forceinline__ void load_tiles(
    __nv_bfloat16* stage,
    const __nv_bfloat16* Ah, const __nv_bfloat16* Al,
    const __nv_bfloat16* Bh, const __nv_bfloat16* Bl,
    int K, int N, int rowBase, int colBase, int k0, int tid)
{
    __nv_bfloat16* sAh = stage;
    __nv_bfloat16* sAl = stage + SA_ELEMS;
    __nv_bfloat16* sBh = stage + 2 * SA_ELEMS;
    __nv_bfloat16* sBl = stage + 2 * SA_ELEMS + SB_ELEMS;
    #pragma unroll
    for (int i = tid; i < 512; i += 256) {
        int r  = i >> 2;
        int cc = (i & 3) * 8;
        size_t g = (size_t)(rowBase + r) * K + k0 + cc;
        int s = r * 40 + cc;
        cp_async16(sAh + s, Ah + g);
        cp_async16(sAl + s, Al + g);
    }
    #pragma unroll
    for (int i = tid; i < 512; i += 256) {
        int r  = i >> 4;
        int cc = (i & 15) * 8;
        size_t g = (size_t)(k0 + r) * N + colBase + cc;
        int s = r * 136 + cc;
        cp_async16(sBh + s, Bh + g);
        cp_async16(sBl + s, Bl + g);
    }
}

__global__ __launch_bounds__(256, 1)
void gemm2_scatter(const __nv_bfloat16* __restrict__ Ah, const __nv_bfloat16* __restrict__ Al,
                   const __nv_bfloat16* __restrict__ Bh, const __nv_bfloat16* __restrict__ Bl,
                   float* __restrict__ C)
{
    extern __shared__ __nv_bfloat16 smem[];
    const int M = RDIM, N = HDIM, K = IDIM;

    const int e = blockIdx.z;
    const __nv_bfloat16* eAh = Ah + (size_t)e * M * K;
    const __nv_bfloat16* eAl = Al + (size_t)e * M * K;
    const __nv_bfloat16* eBh = Bh + (size_t)e * K * N;
    const __nv_bfloat16* eBl = Bl + (size_t)e * K * N;

    const int num_pid_m = M >> 7;
    const int num_pid_n = N >> 7;
    const int pid = blockIdx.x;
    const int num_pid_in_group = GROUP_M * num_pid_n;
    const int group_id = pid / num_pid_in_group;
    const int first_pid_m = group_id * GROUP_M;
    const int group_size_m = min(num_pid_m - first_pid_m, GROUP_M);
    const int pid_m = first_pid_m + (pid % group_size_m);
    const int pid_n = (pid % num_pid_in_group) / group_size_m;

    const int tid  = threadIdx.x;
    const int warp = tid >> 5;
    const int wm   = warp & 3;
    const int wn   = warp >> 2;
    const int rowBase = pid_m * 128;
    const int colBase = pid_n * 128;

    wmma::fragment<wmma::accumulator, 16, 16, 16, float> acc[2][4];
    #pragma unroll
    for (int i = 0; i < 2; ++i)
        #pragma unroll
        for (int j = 0; j < 4; ++j)
            wmma::fill_fragment(acc[i][j], 0.0f);

    const int T = K / 32;

    load_tiles(smem + 0 * STAGE_ELEMS, eAh, eAl, eBh, eBl, K, N, rowBase, colBase, 0, tid);
    cp_commit();
    load_tiles(smem + 1 * STAGE_ELEMS, eAh, eAl, eBh, eBl, K, N, rowBase, colBase, 32, tid);
    cp_commit();
    load_tiles(smem + 2 * STAGE_ELEMS, eAh, eAl, eBh, eBl, K, N, rowBase, colBase, 64, tid);
    cp_commit();

    for (int t = 0; t < T; ++t) {
        if (t + 2 < T)      cp_wait<2>();
        else if (t + 1 < T) cp_wait<1>();
        else                cp_wait<0>();
        __syncthreads();

        if (t + 3 < T) {
            load_tiles(smem + ((t + 3) % NSTAGES) * STAGE_ELEMS,
                       eAh, eAl, eBh, eBl, K, N, rowBase, colBase, (t + 3) * 32, tid);
            cp_commit();
        }

        __nv_bfloat16* stage = smem + (t % NSTAGES) * STAGE_ELEMS;
        const __nv_bfloat16* pAh = stage;
        const __nv_bfloat16* pAl = stage + SA_ELEMS;
        const __nv_bfloat16* pBh = stage + 2 * SA_ELEMS;
        const __nv_bfloat16* pBl = stage + 2 * SA_ELEMS + SB_ELEMS;

        #pragma unroll
        for (int kk = 0; kk < 2; ++kk) {
            wmma::fragment<wmma::matrix_a, 16, 16, 16, __nv_bfloat16, wmma::row_major> ah[2], al[2];
            #pragma unroll
            for (int i = 0; i < 2; ++i) {
                const int ro = (wm * 32 + i * 16) * 40 + kk * 16;
                wmma::load_matrix_sync(ah[i], pAh + ro, 40);
                wmma::load_matrix_sync(al[i], pAl + ro, 40);
            }
            #pragma unroll
            for (int j = 0; j < 4; ++j) {
                wmma::fragment<wmma::matrix_b, 16, 16, 16, __nv_bfloat16, wmma::row_major> bh, bl;
                const int bo = kk * 16 * 136 + wn * 64 + j * 16;
                wmma::load_matrix_sync(bh, pBh + bo, 136);
                wmma::load_matrix_sync(bl, pBl + bo, 136);
                #pragma unroll
                for (int i = 0; i < 2; ++i) {
                    wmma::mma_sync(acc[i][j], ah[i], bh, acc[i][j]);
                    wmma::mma_sync(acc[i][j], al[i], bh, acc[i][j]);
                    wmma::mma_sync(acc[i][j], ah[i], bl, acc[i][j]);
                }
            }
        }
    }

    // Scatter epilogue: r -> token = (r>>9)*2048 + (r&511)*4 + e; within a
    // 16-row fragment consecutive rows are token += 4 => constant ldm 4*2048.
    #pragma unroll
    for (int i = 0; i < 2; ++i) {
        const int r = rowBase + wm * 32 + i * 16;
        const int b = r >> 9;
        const int g = r & 511;
        const size_t tok = (size_t)b * 2048 + (size_t)g * 4 + e;
        #pragma unroll
        for (int j = 0; j < 4; ++j) {
            const int c = colBase + wn * 64 + j * 16;
            float* p = C + tok * 2048 + c;
            wmma::store_matrix_sync(p, acc[i][j], 4 * 2048, wmma::mem_row_major);
        }
    }
}

// ----------------------------- launch ---------------------------------------
extern "C" void kernel_launch(void* const* d_in, const int* in_sizes, int n_in,
                              void* d_out, int out_size) {
    const float* x   = (const float*)d_in[0];   // [8,2048,2048]
    const float* wgu = (const float*)d_in[1];   // [4,2048,4096]
    const float* wd  = (const float*)d_in[2];   // [4,2048,2048]
    float* out = (float*)d_out;                 // [8,2048,2048]

    void *p_xh, *p_xl, *p_wgh, *p_wgl, *p_wdh, *p_wdl, *p_ih, *p_il;
    cudaGetSymbolAddress(&p_xh,  g_xh);
    cudaGetSymbolAddress(&p_xl,  g_xl);
    cudaGetSymbolAddress(&p_wgh, g_wgh);
    cudaGetSymbolAddress(&p_wgl, g_wgl);
    cudaGetSymbolAddress(&p_wdh, g_wdh);
    cudaGetSymbolAddress(&p_wdl, g_wdl);
    cudaGetSymbolAddress(&p_ih,  g_ih);
    cudaGetSymbolAddress(&p_il,  g_il);

    cudaFuncSetAttribute(gemm1_fused,
                         cudaFuncAttributeMaxDynamicSharedMemorySize, SMEM1_BYTES);
    cudaFuncSetAttribute(gemm2_scatter,
                         cudaFuncAttributeMaxDynamicSharedMemorySize, SMEM_BYTES);

    const size_t n_x4   = (size_t)8 * 2048 * 512;      // vec4 counts
    const size_t n_wgu4 = (size_t)4 * 2048 * 1024;
    const size_t n_wd4  = (size_t)4 * 2048 * 512;

    split_x_kernel<<<(unsigned)(n_x4 / 256), 256>>>(
        (const float4*)x, (uint32_t*)p_xh, (uint32_t*)p_xl);
    split_kernel<<<(unsigned)(n_wgu4 / 256), 256>>>(
        (const float4*)wgu, (uint32_t*)p_wgh, (uint32_t*)p_wgl, n_wgu4);
    split_kernel<<<(unsigned)(n_wd4 / 256), 256>>>(
        (const float4*)wd, (uint32_t*)p_wdh, (uint32_t*)p_wdl, n_wd4);

    // GEMM1 fused with silu+split: 32 row-tiles x 32 col-tiles = 1024 CTAs/expert.
    gemm1_fused<<<dim3(32 * 32, 1, EXPERTS), 256, SMEM1_BYTES>>>(
        (const __nv_bfloat16*)p_xh, (const __nv_bfloat16*)p_xl,
        (const __nv_bfloat16*)p_wgh, (const __nv_bfloat16*)p_wgl,
        (__nv_bfloat16*)p_ih, (__nv_bfloat16*)p_il);

    // GEMM2: per expert [4096 x 2048] @ [2048 x 2048] -> scatter into out.
    gemm2_scatter<<<dim3(32 * 16, 1, EXPERTS), 256, SMEM_BYTES>>>(
        (const __nv_bfloat16*)p_ih, (const __nv_bfloat16*)p_il,
        (const __nv_bfloat16*)p_wdh, (const __nv_bfloat16*)p_wdl,
        out);
}

// round 17
// speedup vs baseline: 1.1758x; 1.1758x over previous
#include <cuda_runtime.h>
#include <cuda_bf16.h>
#include <mma.h>
#include <math.h>
#include <cstdint>
#include <cstddef>

using namespace nvcuda;

// ---------------------------------------------------------------------------
// Problem constants: B=8, N=2048, H=2048, E=4, I=2048
// ---------------------------------------------------------------------------
#define EXPERTS 4
#define RDIM    4096          // rows per expert
#define HDIM    2048
#define IDIM    2048

// ---------------------- scratch (__device__ globals) -----------------------
__device__ __nv_bfloat16 g_xh [ (size_t)EXPERTS * RDIM * HDIM ];
__device__ __nv_bfloat16 g_xl [ (size_t)EXPERTS * RDIM * HDIM ];
__device__ __nv_bfloat16 g_wgh[ (size_t)EXPERTS * HDIM * 2 * IDIM ];
__device__ __nv_bfloat16 g_wgl[ (size_t)EXPERTS * HDIM * 2 * IDIM ];
__device__ __nv_bfloat16 g_wdh[ (size_t)EXPERTS * IDIM * HDIM ];
__device__ __nv_bfloat16 g_wdl[ (size_t)EXPERTS * IDIM * HDIM ];
__device__ __nv_bfloat16 g_ih [ (size_t)EXPERTS * RDIM * IDIM ];
__device__ __nv_bfloat16 g_il [ (size_t)EXPERTS * RDIM * IDIM ];

// ---------------------------- helpers --------------------------------------
__device__ __forceinline__ void split2(float v, __nv_bfloat16& hi, __nv_bfloat16& lo) {
    hi = __float2bfloat16(v);
    lo = __float2bfloat16(v - __bfloat162float(hi));
}

__device__ __forceinline__ void split4(float4 v, uint32_t& hi01, uint32_t& hi23,
                                       uint32_t& lo01, uint32_t& lo23) {
    __nv_bfloat16 h0, h1, h2, h3, l0, l1, l2, l3;
    split2(v.x, h0, l0);
    split2(v.y, h1, l1);
    split2(v.z, h2, l2);
    split2(v.w, h3, l3);
    __nv_bfloat162 H01 = __halves2bfloat162(h0, h1);
    __nv_bfloat162 H23 = __halves2bfloat162(h2, h3);
    __nv_bfloat162 L01 = __halves2bfloat162(l0, l1);
    __nv_bfloat162 L23 = __halves2bfloat162(l2, l3);
    hi01 = *(uint32_t*)&H01;  hi23 = *(uint32_t*)&H23;
    lo01 = *(uint32_t*)&L01;  lo23 = *(uint32_t*)&L23;
}

__device__ __forceinline__ float silu_mul(float g, float u) {
    return (g * __frcp_rn(1.0f + __expf(-g))) * u;
}

__device__ __forceinline__ void cp_async16(void* smem, const void* gmem) {
    uint32_t s = (uint32_t)__cvta_generic_to_shared(smem);
    asm volatile("cp.async.cg.shared.global [%0], [%1], 16;\n" :: "r"(s), "l"(gmem));
}
__device__ __forceinline__ void cp_commit() { asm volatile("cp.async.commit_group;\n"); }
template<int NG> __device__ __forceinline__ void cp_wait() {
    asm volatile("cp.async.wait_group %0;\n" :: "n"(NG));
}

// ------------------------- elementwise kernels ------------------------------
__global__ void split_x_kernel(const float4* __restrict__ x,
                               uint32_t* __restrict__ xh,
                               uint32_t* __restrict__ xl) {
    size_t v = (size_t)blockIdx.x * 256 + threadIdx.x;
    int h4 = (int)(v & 511);
    int n  = (int)((v >> 9) & 2047);
    int b  = (int)(v >> 20);
    int e  = n & 3;
    int g  = n >> 2;
    size_t r = (size_t)b * 512 + g;
    size_t dst2 = (((size_t)e * RDIM + r) << 10) + h4 * 2;
    float4 val = x[v];
    uint32_t h01, h23, l01, l23;
    split4(val, h01, h23, l01, l23);
    xh[dst2] = h01;  xh[dst2 + 1] = h23;
    xl[dst2] = l01;  xl[dst2 + 1] = l23;
}

__global__ void split_kernel(const float4* __restrict__ src,
                             uint32_t* __restrict__ h,
                             uint32_t* __restrict__ l,
                             size_t n4) {
    size_t v = (size_t)blockIdx.x * 256 + threadIdx.x;
    if (v >= n4) return;
    uint32_t h01, h23, l01, l23;
    split4(src[v], h01, h23, l01, l23);
    h[v * 2] = h01;  h[v * 2 + 1] = h23;
    l[v * 2] = l01;  l[v * 2 + 1] = l23;
}

// ---------------------------------------------------------------------------
// GEMM1 (fused): A [4096 x 2048] (hi/lo) x Wgu [2048 x 4096] per expert.
// Block tile 128 rows x 64 inter-cols; gate (cols c..c+63) and up
// (cols c+2048..) accumulated together; silu(gate)*up on fragments; split
// to bf16 hi/lo -> ih/il.
// B smem rows pack [gate 64 | up 64 | pad 8] (stride 136) so the stage fits
// 37888 B; 3 stages = 113664 B => 2 CTAs/SM with __launch_bounds__(256,2).
// Pipeline: 3 stages, distance 2, ONE __syncthreads per k-iter.
// ---------------------------------------------------------------------------
#define F_SA    (128 * 40)    // A tile per stream: 128 x (32+8)
#define F_SB    (32 * 136)    // B tile per stream: 32 x (64 gate + 64 up + 8)
#define F_STAGE (2 * F_SA + 2 * F_SB)        // 18944 elems = 37888 B
#define F_NST   3
#define SMEM1_BYTES (F_NST * F_STAGE * 2)    // 113664 B
#define GROUP_M 8

__device__ __forceinline__ void f_load_tiles(
    __nv_bfloat16* stage,
    const __nv_bfloat16* Ah, const __nv_bfloat16* Al,
    const __nv_bfloat16* Bh, const __nv_bfloat16* Bl,
    int rowBase, int colI, int k0, int tid)
{
    __nv_bfloat16* sAh = stage;
    __nv_bfloat16* sAl = stage + F_SA;
    __nv_bfloat16* sBh = stage + 2 * F_SA;
    __nv_bfloat16* sBl = stage + 2 * F_SA + F_SB;
    #pragma unroll
    for (int i = tid; i < 512; i += 256) {        // A: 128x32
        int r  = i >> 2;
        int cc = (i & 3) * 8;
        size_t g = (size_t)(rowBase + r) * HDIM + k0 + cc;
        int s = r * 40 + cc;
        cp_async16(sAh + s, Ah + g);
        cp_async16(sAl + s, Al + g);
    }
    #pragma unroll
    for (int i = tid; i < 512; i += 256) {        // B: 32 rows x (gate64|up64)
        int r  = i >> 4;
        int cc = (i & 15) * 8;                    // 0..120
        // cc<64 -> gate col colI+cc ; cc>=64 -> up col colI+(cc-64)+2048
        size_t g = (size_t)(k0 + r) * (2 * IDIM) + colI + (cc & 63)
                 + ((size_t)(cc >> 6) << 11);
        int s = r * 136 + cc;
        cp_async16(sBh + s, Bh + g);
        cp_async16(sBl + s, Bl + g);
    }
}

__global__ __launch_bounds__(256, 2)
void gemm1_fused(const __nv_bfloat16* __restrict__ Ah, const __nv_bfloat16* __restrict__ Al,
                 const __nv_bfloat16* __restrict__ Bh, const __nv_bfloat16* __restrict__ Bl,
                 __nv_bfloat16* __restrict__ Ih, __nv_bfloat16* __restrict__ Il)
{
    extern __shared__ __nv_bfloat16 smem[];

    const int e = blockIdx.z;
    const __nv_bfloat16* eAh = Ah + (size_t)e * RDIM * HDIM;
    const __nv_bfloat16* eAl = Al + (size_t)e * RDIM * HDIM;
    const __nv_bfloat16* eBh = Bh + (size_t)e * HDIM * 2 * IDIM;
    const __nv_bfloat16* eBl = Bl + (size_t)e * HDIM * 2 * IDIM;

    const int num_pid_m = RDIM / 128;   // 32
    const int num_pid_n = IDIM / 64;    // 32
    const int pid = blockIdx.x;
    const int num_pid_in_group = GROUP_M * num_pid_n;
    const int group_id = pid / num_pid_in_group;
    const int first_pid_m = group_id * GROUP_M;
    const int group_size_m = min(num_pid_m - first_pid_m, GROUP_M);
    const int pid_m = first_pid_m + (pid % group_size_m);
    const int pid_n = (pid % num_pid_in_group) / group_size_m;

    const int tid  = threadIdx.x;
    const int warp = tid >> 5;
    const int lane = tid & 31;
    const int wm   = warp & 3;
    const int wn   = warp >> 2;
    const int rowBase = pid_m * 128;
    const int colI    = pid_n * 64;

    wmma::fragment<wmma::accumulator, 16, 16, 16, float> acc_g[2][2], acc_u[2][2];
    #pragma unroll
    for (int i = 0; i < 2; ++i)
        #pragma unroll
        for (int j = 0; j < 2; ++j) {
            wmma::fill_fragment(acc_g[i][j], 0.0f);
            wmma::fill_fragment(acc_u[i][j], 0.0f);
        }

    const int T = HDIM / 32;   // 64

    f_load_tiles(smem + 0 * F_STAGE, eAh, eAl, eBh, eBl, rowBase, colI, 0, tid);
    cp_commit();
    f_load_tiles(smem + 1 * F_STAGE, eAh, eAl, eBh, eBl, rowBase, colI, 32, tid);
    cp_commit();

    for (int t = 0; t < T; ++t) {
        if (t + 1 < T) cp_wait<1>();
        else           cp_wait<0>();
        __syncthreads();    // stage t ready; all warps done reading (t-1)%3

        if (t + 2 < T) {    // write (t+2)%3 == (t-1)%3, freed by sync above
            f_load_tiles(smem + ((t + 2) % F_NST) * F_STAGE,
                         eAh, eAl, eBh, eBl, rowBase, colI, (t + 2) * 32, tid);
            cp_commit();
        }

        __nv_bfloat16* stage = smem + (t % F_NST) * F_STAGE;
        const __nv_bfloat16* pAh = stage;
        const __nv_bfloat16* pAl = stage + F_SA;
        const __nv_bfloat16* pBh = stage + 2 * F_SA;
        const __nv_bfloat16* pBl = stage + 2 * F_SA + F_SB;

        #pragma unroll
        for (int kk = 0; kk < 2; ++kk) {
            wmma::fragment<wmma::matrix_a, 16, 16, 16, __nv_bfloat16, wmma::row_major> ah[2], al[2];
            #pragma unroll
            for (int i = 0; i < 2; ++i) {
                const int ro = (wm * 32 + i * 16) * 40 + kk * 16;
                wmma::load_matrix_sync(ah[i], pAh + ro, 40);
                wmma::load_matrix_sync(al[i], pAl + ro, 40);
            }
            #pragma unroll
            for (int j = 0; j < 2; ++j) {
                const int bo = kk * 16 * 136 + wn * 32 + j * 16;   // gate
                wmma::fragment<wmma::matrix_b, 16, 16, 16, __nv_bfloat16, wmma::row_major> bh, bl;
                wmma::load_matrix_sync(bh, pBh + bo, 136);
                wmma::load_matrix_sync(bl, pBl + bo, 136);
                #pragma unroll
                for (int i = 0; i < 2; ++i) {
                    wmma::mma_sync(acc_g[i][j], ah[i], bh, acc_g[i][j]);
                    wmma::mma_sync(acc_g[i][j], al[i], bh, acc_g[i][j]);
                    wmma::mma_sync(acc_g[i][j], ah[i], bl, acc_g[i][j]);
                }
                wmma::load_matrix_sync(bh, pBh + bo + 64, 136);    // up
                wmma::load_matrix_sync(bl, pBl + bo + 64, 136);
                #pragma unroll
                for (int i = 0; i < 2; ++i) {
                    wmma::mma_sync(acc_u[i][j], ah[i], bh, acc_u[i][j]);
                    wmma::mma_sync(acc_u[i][j], al[i], bh, acc_u[i][j]);
                    wmma::mma_sync(acc_u[i][j], ah[i], bl, acc_u[i][j]);
                }
            }
        }
    }

    // fused epilogue: inter = silu(gate) * up (fragment layouts identical)
    #pragma unroll
    for (int i = 0; i < 2; ++i)
        #pragma unroll
        for (int j = 0; j < 2; ++j)
            #pragma unroll
            for (int k = 0; k < acc_g[i][j].num_elements; ++k)
                acc_g[i][j].x[k] = silu_mul(acc_g[i][j].x[k], acc_u[i][j].x[k]);

    __syncthreads();   // last mainloop stage fully consumed before smem reuse

    float* ws = (float*)smem + warp * 32 * 36;
    #pragma unroll
    for (int i = 0; i < 2; ++i)
        #pragma unroll
        for (int j = 0; j < 2; ++j)
            wmma::store_matrix_sync(ws + (i * 16) * 36 + j * 16, acc_g[i][j], 36,
                                    wmma::mem_row_major);
    __syncwarp();

    {
        const int r  = rowBase + wm * 32 + lane;
        const int c0 = colI + wn * 32;
        const float* src = ws + lane * 36;
        size_t dst2 = (((size_t)e * RDIM + r) << 10) + (c0 >> 1);
        uint32_t* ih2 = (uint32_t*)Ih;
        uint32_t* il2 = (uint32_t*)Il;
        #pragma unroll
        for (int c = 0; c < 32; c += 4) {
            float4 v = make_float4(src[c], src[c + 1], src[c + 2], src[c + 3]);
            uint32_t h01, h23, l01, l23;
            split4(v, h01, h23, l01, l23);
            ih2[dst2 + (c >> 1)]     = h01;
            ih2[dst2 + (c >> 1) + 1] = h23;
            il2[dst2 + (c >> 1)]     = l01;
            il2[dst2 + (c >> 1) + 1] = l23;
        }
    }
}

// ---------------------------------------------------------------------------
// GEMM2: C = inter (hi/lo) @ Wd (hi/lo), scatter rows to token order.
// Block tile 128x128x32, 8 warps (4x2). 3 stages / distance 2 / one sync.
// 113664 B smem + launch_bounds(256,2) => 2 CTAs/SM.
// ---------------------------------------------------------------------------
#define SA_ELEMS (128 * 40)
#define SB_ELEMS (32 * 136)
#define STAGE_ELEMS (2 * SA_ELEMS + 2 * SB_ELEMS)
#define NSTAGES 3
#define SMEM_BYTES (NSTAGES * STAGE_ELEMS * 2)   // 113664 B

__device__ __forceinline__ void load_tiles(
    __nv_bfloat16* stage,
    const __nv_bfloat16* Ah, const __nv_bfloat16* Al,
    const __nv_bfloat16* Bh, const __nv_bfloat16* Bl,
    int K, int N, int rowBase, int colBase, int k0, int tid)
{
    __nv_bfloat16* sAh = stage;
    __nv_bfloat16* sAl = stage + SA_ELEMS;
    __nv_bfloat16* sBh = stage + 2 * SA_ELEMS;
    __nv_bfloat16* sBl = stage + 2 * SA_ELEMS + SB_ELEMS;
    #pragma unroll
    for (int i = tid; i < 512; i += 256) {
        int r  = i >> 2;
        int cc = (i & 3) * 8;
        size_t g = (size_t)(rowBase + r) * K + k0 + cc;
        int s = r * 40 + cc;
        cp_async16(sAh + s, Ah + g);
        cp_async16(sAl + s, Al + g);
    }
    #pragma unroll
    for (int i = tid; i < 512; i += 256) {
        int r  = i >> 4;
        int cc = (i & 15) * 8;
        size_t g = (size_t)(k0 + r) * N + colBase + cc;
        int s = r * 136 + cc;
        cp_async16(sBh + s, Bh + g);
        cp_async16(sBl + s, Bl + g);
    }
}

__global__ __launch_bounds__(256, 2)
void gemm2_scatter(const __nv_bfloat16* __restrict__ Ah, const __nv_bfloat16* __restrict__ Al,
                   const __nv_bfloat16* __restrict__ Bh, const __nv_bfloat16* __restrict__ Bl,
                   float* __restrict__ C)
{
    extern __shared__ __nv_bfloat16 smem[];
    const int M = RDIM, N = HDIM, K = IDIM;

    const int e = blockIdx.z;
    const __nv_bfloat16* eAh = Ah + (size_t)e * M * K;
    const __nv_bfloat16* eAl = Al + (size_t)e * M * K;
    const __nv_bfloat16* eBh = Bh + (size_t)e * K * N;
    const __nv_bfloat16* eBl = Bl + (size_t)e * K * N;

    const int num_pid_m = M >> 7;
    const int num_pid_n = N >> 7;
    const int pid = blockIdx.x;
    const int num_pid_in_group = GROUP_M * num_pid_n;
    const int group_id = pid / num_pid_in_group;
    const int first_pid_m = group_id * GROUP_M;
    const int group_size_m = min(num_pid_m - first_pid_m, GROUP_M);
    const int pid_m = first_pid_m + (pid % group_size_m);
    const int pid_n = (pid % num_pid_in_group) / group_size_m;

    const int tid  = threadIdx.x;
    const int warp = tid >> 5;
    const int wm   = warp & 3;
    const int wn   = warp >> 2;
    const int rowBase = pid_m * 128;
    const int colBase = pid_n * 128;

    wmma::fragment<wmma::accumulator, 16, 16, 16, float> acc[2][4];
    #pragma unroll
    for (int i = 0; i < 2; ++i)
        #pragma unroll
        for (int j = 0; j < 4; ++j)
            wmma::fill_fragment(acc[i][j], 0.0f);

    const int T = K / 32;

    load_tiles(smem + 0 * STAGE_ELEMS, eAh, eAl, eBh, eBl, K, N, rowBase, colBase, 0, tid);
    cp_commit();
    load_tiles(smem + 1 * STAGE_ELEMS, eAh, eAl, eBh, eBl, K, N, rowBase, colBase, 32, tid);
    cp_commit();

    for (int t = 0; t < T; ++t) {
        if (t + 1 < T) cp_wait<1>();
        else           cp_wait<0>();
        __syncthreads();

        if (t + 2 < T) {
            load_tiles(smem + ((t + 2) % NSTAGES) * STAGE_ELEMS,
                       eAh, eAl, eBh, eBl, K, N, rowBase, colBase, (t + 2) * 32, tid);
            cp_commit();
        }

        __nv_bfloat16* stage = smem + (t % NSTAGES) * STAGE_ELEMS;
        const __nv_bfloat16* pAh = stage;
        const __nv_bfloat16* pAl = stage + SA_ELEMS;
        const __nv_bfloat16* pBh = stage + 2 * SA_ELEMS;
        const __nv_bfloat16* pBl = stage + 2 * SA_ELEMS + SB_ELEMS;

        #pragma unroll
        for (int kk = 0; kk < 2; ++kk) {
            wmma::fragment<wmma::matrix_a, 16, 16, 16, __nv_bfloat16, wmma::row_major> ah[2], al[2];
            #pragma unroll
            for (int i = 0; i < 2; ++i) {
                const int ro = (wm * 32 + i * 16) * 40 + kk * 16;
                wmma::load_matrix_sync(ah[i], pAh + ro, 40);
                wmma::load_matrix_sync(al[i], pAl + ro, 40);
            }
            #pragma unroll
            for (int j = 0; j < 4; ++j) {
                wmma::fragment<wmma::matrix_b, 16, 16, 16, __nv_bfloat16, wmma::row_major> bh, bl;
                const int bo = kk * 16 * 136 + wn * 64 + j * 16;
                wmma::load_matrix_sync(bh, pBh + bo, 136);
                wmma::load_matrix_sync(bl, pBl + bo, 136);
                #pragma unroll
                for (int i = 0; i < 2; ++i) {
                    wmma::mma_sync(acc[i][j], ah[i], bh, acc[i][j]);
                    wmma::mma_sync(acc[i][j], al[i], bh, acc[i][j]);
                    wmma::mma_sync(acc[i][j], ah[i], bl, acc[i][j]);
                }
            }
        }
    }

    // Scatter epilogue: r -> token = (r>>9)*2048 + (r&511)*4 + e
    #pragma unroll
    for (int i = 0; i < 2; ++i) {
        const int r = rowBase + wm * 32 + i * 16;
        const int b = r >> 9;
        const int g = r & 511;
        const size_t tok = (size_t)b * 2048 + (size_t)g * 4 + e;
        #pragma unroll
        for (int j = 0; j < 4; ++j) {
            const int c = colBase + wn * 64 + j * 16;
            float* p = C + tok * 2048 + c;
            wmma::store_matrix_sync(p, acc[i][j], 4 * 2048, wmma::mem_row_major);
        }
    }
}

// ----------------------------- launch ---------------------------------------
extern "C" void kernel_launch(void* const* d_in, const int* in_sizes, int n_in,
                              void* d_out, int out_size) {
    const float* x   = (const float*)d_in[0];
    const float* wgu = (const float*)d_in[1];
    const float* wd  = (const float*)d_in[2];
    float* out = (float*)d_out;

    void *p_xh, *p_xl, *p_wgh, *p_wgl, *p_wdh, *p_wdl, *p_ih, *p_il;
    cudaGetSymbolAddress(&p_xh,  g_xh);
    cudaGetSymbolAddress(&p_xl,  g_xl);
    cudaGetSymbolAddress(&p_wgh, g_wgh);
    cudaGetSymbolAddress(&p_wgl, g_wgl);
    cudaGetSymbolAddress(&p_wdh, g_wdh);
    cudaGetSymbolAddress(&p_wdl, g_wdl);
    cudaGetSymbolAddress(&p_ih,  g_ih);
    cudaGetSymbolAddress(&p_il,  g_il);

    cudaFuncSetAttribute(gemm1_fused,
                         cudaFuncAttributeMaxDynamicSharedMemorySize, SMEM1_BYTES);
    cudaFuncSetAttribute(gemm2_scatter,
                         cudaFuncAttributeMaxDynamicSharedMemorySize, SMEM_BYTES);

    const size_t n_x4   = (size_t)8 * 2048 * 512;
    const size_t n_wgu4 = (size_t)4 * 2048 * 1024;
    const size_t n_wd4  = (size_t)4 * 2048 * 512;

    split_x_kernel<<<(unsigned)(n_x4 / 256), 256>>>(
        (const float4*)x, (uint32_t*)p_xh, (uint32_t*)p_xl);
    split_kernel<<<(unsigned)(n_wgu4 / 256), 256>>>(
        (const float4*)wgu, (uint32_t*)p_wgh, (uint32_t*)p_wgl, n_wgu4);
    split_kernel<<<(unsigned)(n_wd4 / 256), 256>>>(
        (const float4*)wd, (uint32_t*)p_wdh, (uint32_t*)p_wdl, n_wd4);

    gemm1_fused<<<dim3(32 * 32, 1, EXPERTS), 256, SMEM1_BYTES>>>(
        (const __nv_bfloat16*)p_xh, (const __nv_bfloat16*)p_xl,
        (const __nv_bfloat16*)p_wgh, (const __nv_bfloat16*)p_wgl,
        (__nv_bfloat16*)p_ih, (__nv_bfloat16*)p_il);

    gemm2_scatter<<<dim3(32 * 16, 1, EXPERTS), 256, SMEM_BYTES>>>(
        (const __nv_bfloat16*)p_ih, (const __nv_bfloat16*)p_il,
        (const __nv_bfloat16*)p_wdh, (const __nv_bfloat16*)p_wdl,
        out);
}